// round 15
// baseline (speedup 1.0000x reference)
#include <cuda_runtime.h>
#include <cuda_bf16.h>
#include <cuda_fp16.h>
#include <cstdint>

// Problem constants
#define BB 2
#define NN 2048
#define DDIM 1024
#define HH 16
#define HD 64
#define MROWS (BB * NN)   // 4096
#define N3D (3 * DDIM)    // 3072

// ---------------------------------------------------------------------------
// Scratch (no allocations allowed)
// ---------------------------------------------------------------------------
__device__ __align__(128) __half g_ah[MROWS * DDIM];   // activations fp16 (hs, later attn out)
__device__ __align__(128) __half g_wqt[N3D * DDIM];    // W_attn^T fp16 [N][K]
__device__ __align__(128) __half g_wpt[DDIM * DDIM];   // W_proj^T fp16 [N][K]
__device__ __align__(128) __half g_qf[MROWS * DDIM];   // q fp16 head-major, prescaled
__device__ __align__(128) __half g_kf[MROWS * DDIM];   // k fp16 head-major
__device__ __align__(128) __half g_vtf[MROWS * DDIM];  // V^T fp16 [bh][64][2048]

// ---------------------------------------------------------------------------
// Baseline-PTX tensor-core helpers
// ---------------------------------------------------------------------------
__device__ __forceinline__ uint32_t smem_u32(const void* p) {
    uint32_t a;
    asm("{ .reg .u64 t; cvta.to.shared.u64 t, %1; cvt.u32.u64 %0, t; }"
        : "=r"(a) : "l"(p));
    return a;
}
__device__ __forceinline__ void ldsm4(uint32_t r[4], uint32_t addr) {
    asm volatile("ldmatrix.sync.aligned.m8n8.x4.shared.b16 {%0,%1,%2,%3}, [%4];"
                 : "=r"(r[0]), "=r"(r[1]), "=r"(r[2]), "=r"(r[3]) : "r"(addr));
}
__device__ __forceinline__ void mma16816h(float c[4], const uint32_t a[4],
                                          uint32_t b0, uint32_t b1) {
    asm volatile(
        "mma.sync.aligned.m16n8k16.row.col.f32.f16.f16.f32 "
        "{%0,%1,%2,%3}, {%4,%5,%6,%7}, {%8,%9}, {%0,%1,%2,%3};"
        : "+f"(c[0]), "+f"(c[1]), "+f"(c[2]), "+f"(c[3])
        : "r"(a[0]), "r"(a[1]), "r"(a[2]), "r"(a[3]), "r"(b0), "r"(b1));
}
__device__ __forceinline__ void cp16(uint32_t dst, const void* src) {
    asm volatile("cp.async.cg.shared.global [%0], [%1], 16;"
                 :: "r"(dst), "l"(src) : "memory");
}
#define CP_COMMIT() asm volatile("cp.async.commit_group;" ::: "memory")
#define CP_WAIT1()  asm volatile("cp.async.wait_group 1;" ::: "memory")

__device__ __forceinline__ uint32_t packhf(float x, float y) {
    __half2 t = __floats2half2_rn(x, y);
    return *(uint32_t*)&t;
}

// ---------------------------------------------------------------------------
// Fused prep: one kernel does
//   blocks [0, 4096)            : hs fp32 -> fp16 (elementwise, float4)
//   blocks [4096, 4096+3072)    : W_attn [K,N] -> [N,K] fp16 transpose
//   blocks [7168, 7168+1024)    : W_proj [K,N] -> [N,K] fp16 transpose
// ---------------------------------------------------------------------------
#define PREP_CONV_BLKS  (MROWS * DDIM / 4 / 256)        // 4096
#define PREP_WA_BLKS    ((N3D / 32) * (DDIM / 32))       // 3072
#define PREP_WP_BLKS    ((DDIM / 32) * (DDIM / 32))      // 1024
#define PREP_BLKS       (PREP_CONV_BLKS + PREP_WA_BLKS + PREP_WP_BLKS)

__device__ __forceinline__ void transpose_tile(const float* __restrict__ W,
                                               __half* __restrict__ T,
                                               int K, int N, int n0, int k0) {
    __shared__ float t[32][33];
    const int tid = threadIdx.x;
    const int tx = tid & 31, ty = tid >> 5;  // 32 x 8
    #pragma unroll
    for (int i = 0; i < 4; i++)
        t[ty + i * 8][tx] = W[(size_t)(k0 + ty + i * 8) * N + n0 + tx];
    __syncthreads();
    #pragma unroll
    for (int i = 0; i < 4; i++) {
        int r = ty + i * 8;
        T[(size_t)(n0 + r) * K + k0 + tx] = __float2half_rn(t[tx][r]);
    }
}

__global__ __launch_bounds__(256) void prep_all(
    const float* __restrict__ hs,
    const float* __restrict__ W_attn, const float* __restrict__ W_proj,
    __half* __restrict__ ah, __half* __restrict__ wqt, __half* __restrict__ wpt)
{
    const int bid = blockIdx.x;
    if (bid < PREP_CONV_BLKS) {
        int i = bid * 256 + threadIdx.x;
        float4 v = ((const float4*)hs)[i];
        ((__half2*)ah)[2 * i]     = __floats2half2_rn(v.x, v.y);
        ((__half2*)ah)[2 * i + 1] = __floats2half2_rn(v.z, v.w);
    } else if (bid < PREP_CONV_BLKS + PREP_WA_BLKS) {
        int l = bid - PREP_CONV_BLKS;
        int n0 = (l % (N3D / 32)) * 32;
        int k0 = (l / (N3D / 32)) * 32;
        transpose_tile(W_attn, wqt, DDIM, N3D, n0, k0);
    } else {
        int l = bid - PREP_CONV_BLKS - PREP_WA_BLKS;
        int n0 = (l % (DDIM / 32)) * 32;
        int k0 = (l / (DDIM / 32)) * 32;
        transpose_tile(W_proj, wpt, DDIM, DDIM, n0, k0);
    }
}

// ---------------------------------------------------------------------------
// Shared GEMM mainloop (fp16 single product, 3-stage cp.async):
// acc = A[M,1024] @ B^T, B as [NTOT][1024] fp16 k-major.
// CTA 128x128, 512 threads (16 warps, 4x4, 32x32/warp), BK=32.
// ---------------------------------------------------------------------------
#define TILE_B    10240
#define F16_STAGE (2 * TILE_B)    // 20480
#define F16_SMEM  (3 * F16_STAGE) // 61440

struct GemmCtx {
    int lane, wm, wn, bm, bn;
};

__device__ __forceinline__ void gemm_mainloop_f16(
    char* sm, const __half* __restrict__ A, const __half* __restrict__ B,
    GemmCtx& cx, float acc[2][4][4])
{
    const uint32_t smb = smem_u32(sm);
    const int tid = threadIdx.x;
    const int lane = tid & 31;
    const int wid = tid >> 5;
    cx.lane = lane;
    cx.wm = wid & 3;
    cx.wn = wid >> 2;
    cx.bm = blockIdx.y * 128;
    cx.bn = blockIdx.x * 128;

    #pragma unroll
    for (int i = 0; i < 2; i++)
        #pragma unroll
        for (int j = 0; j < 4; j++)
            #pragma unroll
            for (int k = 0; k < 4; k++) acc[i][j][k] = 0.f;

    const int lrow = tid >> 2;
    const int lc   = tid & 3;
    #define F16_LOAD(stg, k0)                                                     \
        do {                                                                      \
            uint32_t st_ = smb + (stg) * F16_STAGE;                               \
            uint32_t doff_ = (uint32_t)(lrow * 80 + lc * 16);                     \
            cp16(st_ + doff_,          A + (size_t)(cx.bm + lrow) * 1024 + (k0) + lc * 8); \
            cp16(st_ + TILE_B + doff_, B + (size_t)(cx.bn + lrow) * 1024 + (k0) + lc * 8); \
        } while (0)

    const uint32_t a_roff = (uint32_t)((cx.wm * 32 + (lane & 15)) * 80 + (lane >> 4) * 16);
    const uint32_t b_row  = (uint32_t)((lane & 7) | ((lane & 16) >> 1));
    const uint32_t b_roff = (uint32_t)((cx.wn * 32 + b_row) * 80 + ((lane >> 3) & 1) * 16);

    F16_LOAD(0, 0);
    CP_COMMIT();
    F16_LOAD(1, 32);
    CP_COMMIT();

    const int NIT = 1024 / 32;
    int stg = 0;
    for (int it = 0; it < NIT; it++) {
        CP_WAIT1();
        __syncthreads();
        if (it + 2 < NIT) F16_LOAD((stg + 2) % 3, (it + 2) * 32);
        CP_COMMIT();

        const uint32_t sA = smb + stg * F16_STAGE;
        const uint32_t sB = sA + TILE_B;

        #pragma unroll
        for (int ks = 0; ks < 2; ks++) {
            uint32_t af[2][4], bf_[2][4];
            uint32_t ao = a_roff + ks * 32;
            ldsm4(af[0], sA + ao);
            ldsm4(af[1], sA + ao + 16 * 80);
            uint32_t bo = b_roff + ks * 32;
            ldsm4(bf_[0], sB + bo);
            ldsm4(bf_[1], sB + bo + 16 * 80);
            #pragma unroll
            for (int mf = 0; mf < 2; mf++)
                #pragma unroll
                for (int nf = 0; nf < 4; nf++) {
                    int g = nf >> 1, o = (nf & 1) * 2;
                    mma16816h(acc[mf][nf], af[mf], bf_[g][o], bf_[g][o + 1]);
                }
        }
        stg = (stg + 1) % 3;
    }
    #undef F16_LOAD
}

// ---------------------------------------------------------------------------
// QKV GEMM with fused repack epilogue: writes q (fp16 head-major, x0.125),
// k (fp16 head-major), v^T (fp16 [bh][d][n]) directly.
// ---------------------------------------------------------------------------
__global__ __launch_bounds__(512, 2) void tc_gemm_qkv(
    const __half* __restrict__ A, const __half* __restrict__ B,
    const float* __restrict__ bias,
    __half* __restrict__ qf, __half* __restrict__ kf, __half* __restrict__ vtf)
{
    extern __shared__ char sm[];
    GemmCtx cx;
    float acc[2][4][4];
    gemm_mainloop_f16(sm, A, B, cx, acc);

    const int region = cx.bn >> 10;          // 0=q, 1=k, 2=v
    const int rbase = cx.bm + cx.wm * 32 + (cx.lane >> 2);
    #pragma unroll
    for (int nf = 0; nf < 4; nf++) {
        int col = cx.bn + cx.wn * 32 + nf * 8 + (cx.lane & 3) * 2;
        float b0 = __ldg(&bias[col]);
        float b1 = __ldg(&bias[col + 1]);
        int c = col & 1023;
        int h = c >> 6, d = c & 63;
        #pragma unroll
        for (int mf = 0; mf < 2; mf++) {
            #pragma unroll
            for (int rr = 0; rr < 2; rr++) {
                int row = rbase + mf * 16 + rr * 8;
                float x0 = acc[mf][nf][rr * 2 + 0] + b0;
                float x1 = acc[mf][nf][rr * 2 + 1] + b1;
                int b = row >> 11, n = row & 2047;
                if (region == 0) {
                    size_t oi = ((size_t)(b * HH + h) * NN + n) * HD + d;
                    *(__half2*)(qf + oi) = __floats2half2_rn(x0 * 0.125f, x1 * 0.125f);
                } else if (region == 1) {
                    size_t oi = ((size_t)(b * HH + h) * NN + n) * HD + d;
                    *(__half2*)(kf + oi) = __floats2half2_rn(x0, x1);
                } else {
                    size_t oi = ((size_t)(b * HH + h) * HD + d) * NN + n;
                    vtf[oi]      = __float2half_rn(x0);
                    vtf[oi + NN] = __float2half_rn(x1);
                }
            }
        }
    }
}

// ---------------------------------------------------------------------------
// Output projection GEMM (standard fp32 epilogue to d_out)
// ---------------------------------------------------------------------------
__global__ __launch_bounds__(512, 2) void tc_gemm_proj(
    const __half* __restrict__ A, const __half* __restrict__ B,
    const float* __restrict__ bias, float* __restrict__ C)
{
    extern __shared__ char sm[];
    GemmCtx cx;
    float acc[2][4][4];
    gemm_mainloop_f16(sm, A, B, cx, acc);

    #pragma unroll
    for (int nf = 0; nf < 4; nf++) {
        int col = cx.bn + cx.wn * 32 + nf * 8 + (cx.lane & 3) * 2;
        float b0 = __ldg(&bias[col]);
        float b1 = __ldg(&bias[col + 1]);
        #pragma unroll
        for (int mf = 0; mf < 2; mf++) {
            int row0 = cx.bm + cx.wm * 32 + mf * 16 + (cx.lane >> 2);
            float2 v0 = make_float2(acc[mf][nf][0] + b0, acc[mf][nf][1] + b1);
            float2 v1 = make_float2(acc[mf][nf][2] + b0, acc[mf][nf][3] + b1);
            *(float2*)&C[(size_t)row0 * DDIM + col]       = v0;
            *(float2*)&C[(size_t)(row0 + 8) * DDIM + col] = v1;
        }
    }
}

// ---------------------------------------------------------------------------
// Flash attention via fp16 mma.sync (S single, P single x V single).
// __launch_bounds__(256, 2): 2 CTAs/SM so one CTA's softmax overlaps the
// other's MMA. Epilogue writes fp16 directly into g_ah.
// ---------------------------------------------------------------------------
#define AT_KSTR 72
#define AT_VSTR 136
#define AT_K_B  (128 * AT_KSTR * 2)
#define AT_V_B  (64 * AT_VSTR * 2)
#define AT_STAGE_B (AT_K_B + AT_V_B)                // 35840 bytes
#define ATT_SMEM (2 * AT_STAGE_B)                   // 71680 bytes

__global__ __launch_bounds__(256, 2) void attn_mma(
    const __half* __restrict__ qf, const __half* __restrict__ kf,
    const __half* __restrict__ vtf, __half* __restrict__ outh)
{
    extern __shared__ __half sbh[];
    __half* sK0 = sbh;
    const uint32_t aK = smem_u32(sK0);
    const uint32_t aV = aK + AT_K_B;

    const int tid = threadIdx.x, lane = tid & 31, w = tid >> 5;
    const int qt = 15 - (int)blockIdx.x;
    const int bh = blockIdx.y;
    const int b = bh >> 4, h = bh & 15;
    const size_t hb = (size_t)bh * (NN * HD);
    const size_t vb = (size_t)bh * (HD * NN);

    const int r8  = tid >> 3, c8 = tid & 7;
    const int r16v = tid >> 4, c16v = tid & 15;
    const uint32_t brow = (uint32_t)((lane & 7) | ((lane & 16) >> 1));
    const uint32_t bcol8 = (uint32_t)(((lane >> 3) & 1) * 8);

    #define AT_LOAD(stg_, kt_)                                                    \
        do {                                                                      \
            uint32_t kb_ = (uint32_t)(stg_) * AT_STAGE_B;                         \
            int kv0_ = (kt_) * 128;                                               \
            _Pragma("unroll")                                                     \
            for (int i_ = 0; i_ < 4; i_++) {                                      \
                int r_ = i_ * 32 + r8;                                            \
                cp16(aK + kb_ + (uint32_t)(r_ * AT_KSTR + c8 * 8) * 2,            \
                     kf + hb + (size_t)(kv0_ + r_) * HD + c8 * 8);                \
            }                                                                     \
            _Pragma("unroll")                                                     \
            for (int i_ = 0; i_ < 4; i_++) {                                      \
                int d_ = i_ * 16 + r16v;                                          \
                cp16(aV + kb_ + (uint32_t)(d_ * AT_VSTR + c16v * 8) * 2,          \
                     vtf + vb + (size_t)d_ * NN + kv0_ + c16v * 8);               \
            }                                                                     \
        } while (0)

    // ---- stage Q into stage-0 K buffer, extract A-frags ----
    #pragma unroll
    for (int i = 0; i < 4; i++) {
        int r = i * 32 + r8;
        size_t g = hb + (size_t)(qt * 128 + r) * HD + c8 * 8;
        *(uint4*)(sK0 + r * AT_KSTR + c8 * 8) = *(const uint4*)(qf + g);
    }
    __syncthreads();
    uint32_t qfr[4][4];
    #pragma unroll
    for (int ks = 0; ks < 4; ks++) {
        uint32_t off = (uint32_t)(((w * 16 + (lane & 15)) * AT_KSTR
                                   + (lane >> 4) * 8 + ks * 16) * 2);
        ldsm4(qfr[ks], aK + off);
    }
    __syncthreads();

    float m0 = -1e30f, m1 = -1e30f, l0 = 0.f, l1 = 0.f;
    float o[8][4];
    #pragma unroll
    for (int i = 0; i < 8; i++)
        #pragma unroll
        for (int j = 0; j < 4; j++) o[i][j] = 0.f;

    const int nkv = qt + 1;
    AT_LOAD(0, 0);
    CP_COMMIT();

    for (int kt = 0; kt < nkv; kt++) {
        const int stg = kt & 1;
        if (kt + 1 < nkv) AT_LOAD(stg ^ 1, kt + 1);
        CP_COMMIT();
        CP_WAIT1();
        __syncthreads();

        const uint32_t kb = (uint32_t)stg * AT_STAGE_B;
        const uint32_t bK = aK + kb, bV = aV + kb;

        float s[16][4];
        #pragma unroll
        for (int i = 0; i < 16; i++)
            #pragma unroll
            for (int j = 0; j < 4; j++) s[i][j] = 0.f;

        #pragma unroll
        for (int g = 0; g < 8; g++) {
            #pragma unroll
            for (int ks = 0; ks < 4; ks++) {
                uint32_t kfr[4];
                uint32_t off = (uint32_t)((((g * 16) + brow) * AT_KSTR
                                           + bcol8 + ks * 16) * 2);
                ldsm4(kfr, bK + off);
                #pragma unroll
                for (int nf2 = 0; nf2 < 2; nf2++)
                    mma16816h(s[g * 2 + nf2], qfr[ks], kfr[nf2 * 2], kfr[nf2 * 2 + 1]);
            }
        }

        if (kt == qt) {
            int row0 = w * 16 + (lane >> 2);
            #pragma unroll
            for (int nf = 0; nf < 16; nf++) {
                int col = nf * 8 + (lane & 3) * 2;
                if (col > row0)     s[nf][0] = -1e30f;
                if (col + 1 > row0) s[nf][1] = -1e30f;
                if (col > row0 + 8)     s[nf][2] = -1e30f;
                if (col + 1 > row0 + 8) s[nf][3] = -1e30f;
            }
        }

        float mt0 = -1e30f, mt1 = -1e30f;
        #pragma unroll
        for (int nf = 0; nf < 16; nf++) {
            mt0 = fmaxf(mt0, fmaxf(s[nf][0], s[nf][1]));
            mt1 = fmaxf(mt1, fmaxf(s[nf][2], s[nf][3]));
        }
        mt0 = fmaxf(mt0, __shfl_xor_sync(0xffffffffu, mt0, 1));
        mt0 = fmaxf(mt0, __shfl_xor_sync(0xffffffffu, mt0, 2));
        mt1 = fmaxf(mt1, __shfl_xor_sync(0xffffffffu, mt1, 1));
        mt1 = fmaxf(mt1, __shfl_xor_sync(0xffffffffu, mt1, 2));
        float mn0 = fmaxf(m0, mt0), mn1 = fmaxf(m1, mt1);
        float cr0 = __expf(m0 - mn0), cr1 = __expf(m1 - mn1);
        float rs0 = 0.f, rs1 = 0.f;
        #pragma unroll
        for (int nf = 0; nf < 16; nf++) {
            s[nf][0] = __expf(s[nf][0] - mn0);
            s[nf][1] = __expf(s[nf][1] - mn0);
            s[nf][2] = __expf(s[nf][2] - mn1);
            s[nf][3] = __expf(s[nf][3] - mn1);
            rs0 += s[nf][0] + s[nf][1];
            rs1 += s[nf][2] + s[nf][3];
        }
        rs0 += __shfl_xor_sync(0xffffffffu, rs0, 1);
        rs0 += __shfl_xor_sync(0xffffffffu, rs0, 2);
        rs1 += __shfl_xor_sync(0xffffffffu, rs1, 1);
        rs1 += __shfl_xor_sync(0xffffffffu, rs1, 2);
        l0 = l0 * cr0 + rs0;
        l1 = l1 * cr1 + rs1;
        m0 = mn0; m1 = mn1;
        #pragma unroll
        for (int nf = 0; nf < 8; nf++) {
            o[nf][0] *= cr0; o[nf][1] *= cr0;
            o[nf][2] *= cr1; o[nf][3] *= cr1;
        }

        // ---- O += P V : P fp16 single, V fp16 single ----
        #pragma unroll
        for (int ks2 = 0; ks2 < 8; ks2++) {
            uint32_t pa[4];
            {
                const float* s0 = s[2 * ks2];
                const float* s1 = s[2 * ks2 + 1];
                pa[0] = packhf(s0[0], s0[1]);
                pa[1] = packhf(s0[2], s0[3]);
                pa[2] = packhf(s1[0], s1[1]);
                pa[3] = packhf(s1[2], s1[3]);
            }
            #pragma unroll
            for (int g = 0; g < 4; g++) {
                uint32_t vfr[4];
                uint32_t off = (uint32_t)((((g * 16) + brow) * AT_VSTR
                                           + bcol8 + ks2 * 16) * 2);
                ldsm4(vfr, bV + off);
                #pragma unroll
                for (int nf2 = 0; nf2 < 2; nf2++) {
                    int nf = g * 2 + nf2, oo = nf2 * 2;
                    mma16816h(o[nf], pa, vfr[oo], vfr[oo + 1]);
                }
            }
        }
        __syncthreads();
    }

    // finalize: write fp16 directly into proj input buffer
    float inv0 = 1.f / l0, inv1 = 1.f / l1;
    const int row0 = b * NN + qt * 128 + w * 16 + (lane >> 2);
    #pragma unroll
    for (int nf = 0; nf < 8; nf++) {
        int col = h * HD + nf * 8 + (lane & 3) * 2;
        *(__half2*)&outh[(size_t)row0 * DDIM + col] =
            __floats2half2_rn(o[nf][0] * inv0, o[nf][1] * inv0);
        *(__half2*)&outh[(size_t)(row0 + 8) * DDIM + col] =
            __floats2half2_rn(o[nf][2] * inv1, o[nf][3] * inv1);
    }
}

// ---------------------------------------------------------------------------
// Launch
// ---------------------------------------------------------------------------
extern "C" void kernel_launch(void* const* d_in, const int* in_sizes, int n_in,
                              void* d_out, int out_size) {
    const float* hs     = (const float*)d_in[0];
    const float* W_attn = (const float*)d_in[1];
    const float* b_attn = (const float*)d_in[2];
    const float* W_proj = (const float*)d_in[3];
    const float* b_proj = (const float*)d_in[4];
    float* out = (float*)d_out;

    cudaFuncSetAttribute(attn_mma,
                         cudaFuncAttributeMaxDynamicSharedMemorySize, ATT_SMEM);
    cudaFuncSetAttribute(tc_gemm_qkv,
                         cudaFuncAttributeMaxDynamicSharedMemorySize, F16_SMEM);
    cudaFuncSetAttribute(tc_gemm_proj,
                         cudaFuncAttributeMaxDynamicSharedMemorySize, F16_SMEM);

    __half *ah, *wqt, *wpt, *qf, *kf, *vtf;
    cudaGetSymbolAddress((void**)&ah,   g_ah);
    cudaGetSymbolAddress((void**)&wqt,  g_wqt);
    cudaGetSymbolAddress((void**)&wpt,  g_wpt);
    cudaGetSymbolAddress((void**)&qf,   g_qf);
    cudaGetSymbolAddress((void**)&kf,   g_kf);
    cudaGetSymbolAddress((void**)&vtf,  g_vtf);

    // 1) fused prep: hs->fp16 + both weight transposes
    prep_all<<<PREP_BLKS, 256>>>(hs, W_attn, W_proj, ah, wqt, wpt);
    // 2) QKV projection + fused q/k/v repack
    tc_gemm_qkv<<<dim3(N3D / 128, MROWS / 128), 512, F16_SMEM>>>(
        ah, wqt, b_attn, qf, kf, vtf);
    // 3) causal flash attention (fp16 tensor cores), writes fp16 into g_ah
    attn_mma<<<dim3(NN / 128, BB * HH), 256, ATT_SMEM>>>(qf, kf, vtf, ah);
    // 4) output projection
    tc_gemm_proj<<<dim3(DDIM / 128, MROWS / 128), 512, F16_SMEM>>>(
        ah, wpt, b_proj, out);
}

// round 16
// speedup vs baseline: 1.0336x; 1.0336x over previous
#include <cuda_runtime.h>
#include <cuda_bf16.h>
#include <cuda_fp16.h>
#include <cstdint>

// Problem constants
#define BB 2
#define NN 2048
#define DDIM 1024
#define HH 16
#define HD 64
#define MROWS (BB * NN)   // 4096
#define N3D (3 * DDIM)    // 3072

// ---------------------------------------------------------------------------
// Scratch (no allocations allowed)
// ---------------------------------------------------------------------------
__device__ __align__(128) __half g_ah[MROWS * DDIM];   // activations fp16 (hs, later attn out)
__device__ __align__(128) __half g_wqt[N3D * DDIM];    // W_attn^T fp16 [N][K]
__device__ __align__(128) __half g_wpt[DDIM * DDIM];   // W_proj^T fp16 [N][K]
__device__ __align__(128) __half g_qf[MROWS * DDIM];   // q fp16 head-major, prescaled
__device__ __align__(128) __half g_kf[MROWS * DDIM];   // k fp16 head-major
__device__ __align__(128) __half g_vtf[MROWS * DDIM];  // V^T fp16 [bh][64][2048]

// ---------------------------------------------------------------------------
// Baseline-PTX tensor-core helpers
// ---------------------------------------------------------------------------
__device__ __forceinline__ uint32_t smem_u32(const void* p) {
    uint32_t a;
    asm("{ .reg .u64 t; cvta.to.shared.u64 t, %1; cvt.u32.u64 %0, t; }"
        : "=r"(a) : "l"(p));
    return a;
}
__device__ __forceinline__ void ldsm4(uint32_t r[4], uint32_t addr) {
    asm volatile("ldmatrix.sync.aligned.m8n8.x4.shared.b16 {%0,%1,%2,%3}, [%4];"
                 : "=r"(r[0]), "=r"(r[1]), "=r"(r[2]), "=r"(r[3]) : "r"(addr));
}
__device__ __forceinline__ void mma16816h(float c[4], const uint32_t a[4],
                                          uint32_t b0, uint32_t b1) {
    asm volatile(
        "mma.sync.aligned.m16n8k16.row.col.f32.f16.f16.f32 "
        "{%0,%1,%2,%3}, {%4,%5,%6,%7}, {%8,%9}, {%0,%1,%2,%3};"
        : "+f"(c[0]), "+f"(c[1]), "+f"(c[2]), "+f"(c[3])
        : "r"(a[0]), "r"(a[1]), "r"(a[2]), "r"(a[3]), "r"(b0), "r"(b1));
}
__device__ __forceinline__ void cp16(uint32_t dst, const void* src) {
    asm volatile("cp.async.cg.shared.global [%0], [%1], 16;"
                 :: "r"(dst), "l"(src) : "memory");
}
#define CP_COMMIT() asm volatile("cp.async.commit_group;" ::: "memory")
#define CP_WAIT1()  asm volatile("cp.async.wait_group 1;" ::: "memory")

__device__ __forceinline__ uint32_t packhf(float x, float y) {
    __half2 t = __floats2half2_rn(x, y);
    return *(uint32_t*)&t;
}

// ---------------------------------------------------------------------------
// Fused prep: one kernel does
//   blocks [0, 4096)            : hs fp32 -> fp16 (elementwise, float4)
//   blocks [4096, 4096+3072)    : W_attn [K,N] -> [N,K] fp16 transpose
//   blocks [7168, 7168+1024)    : W_proj [K,N] -> [N,K] fp16 transpose
// ---------------------------------------------------------------------------
#define PREP_CONV_BLKS  (MROWS * DDIM / 4 / 256)        // 4096
#define PREP_WA_BLKS    ((N3D / 32) * (DDIM / 32))       // 3072
#define PREP_WP_BLKS    ((DDIM / 32) * (DDIM / 32))      // 1024
#define PREP_BLKS       (PREP_CONV_BLKS + PREP_WA_BLKS + PREP_WP_BLKS)

__device__ __forceinline__ void transpose_tile(const float* __restrict__ W,
                                               __half* __restrict__ T,
                                               int K, int N, int n0, int k0) {
    __shared__ float t[32][33];
    const int tid = threadIdx.x;
    const int tx = tid & 31, ty = tid >> 5;  // 32 x 8
    #pragma unroll
    for (int i = 0; i < 4; i++)
        t[ty + i * 8][tx] = W[(size_t)(k0 + ty + i * 8) * N + n0 + tx];
    __syncthreads();
    #pragma unroll
    for (int i = 0; i < 4; i++) {
        int r = ty + i * 8;
        T[(size_t)(n0 + r) * K + k0 + tx] = __float2half_rn(t[tx][r]);
    }
}

__global__ __launch_bounds__(256) void prep_all(
    const float* __restrict__ hs,
    const float* __restrict__ W_attn, const float* __restrict__ W_proj,
    __half* __restrict__ ah, __half* __restrict__ wqt, __half* __restrict__ wpt)
{
    const int bid = blockIdx.x;
    if (bid < PREP_CONV_BLKS) {
        int i = bid * 256 + threadIdx.x;
        float4 v = ((const float4*)hs)[i];
        ((__half2*)ah)[2 * i]     = __floats2half2_rn(v.x, v.y);
        ((__half2*)ah)[2 * i + 1] = __floats2half2_rn(v.z, v.w);
    } else if (bid < PREP_CONV_BLKS + PREP_WA_BLKS) {
        int l = bid - PREP_CONV_BLKS;
        int n0 = (l % (N3D / 32)) * 32;
        int k0 = (l / (N3D / 32)) * 32;
        transpose_tile(W_attn, wqt, DDIM, N3D, n0, k0);
    } else {
        int l = bid - PREP_CONV_BLKS - PREP_WA_BLKS;
        int n0 = (l % (DDIM / 32)) * 32;
        int k0 = (l / (DDIM / 32)) * 32;
        transpose_tile(W_proj, wpt, DDIM, DDIM, n0, k0);
    }
}

// ---------------------------------------------------------------------------
// Shared GEMM mainloop (fp16 single product, 3-stage cp.async):
// acc = A[M,1024] @ B^T, B as [NTOT][1024] fp16 k-major.
// CTA 128x128, 512 threads (16 warps, 4x4, 32x32/warp), BK=32.
// ---------------------------------------------------------------------------
#define TILE_B    10240
#define F16_STAGE (2 * TILE_B)    // 20480
#define F16_SMEM  (3 * F16_STAGE) // 61440

struct GemmCtx {
    int lane, wm, wn, bm, bn;
};

__device__ __forceinline__ void gemm_mainloop_f16(
    char* sm, const __half* __restrict__ A, const __half* __restrict__ B,
    GemmCtx& cx, float acc[2][4][4])
{
    const uint32_t smb = smem_u32(sm);
    const int tid = threadIdx.x;
    const int lane = tid & 31;
    const int wid = tid >> 5;
    cx.lane = lane;
    cx.wm = wid & 3;
    cx.wn = wid >> 2;
    cx.bm = blockIdx.y * 128;
    cx.bn = blockIdx.x * 128;

    #pragma unroll
    for (int i = 0; i < 2; i++)
        #pragma unroll
        for (int j = 0; j < 4; j++)
            #pragma unroll
            for (int k = 0; k < 4; k++) acc[i][j][k] = 0.f;

    const int lrow = tid >> 2;
    const int lc   = tid & 3;
    #define F16_LOAD(stg, k0)                                                     \
        do {                                                                      \
            uint32_t st_ = smb + (stg) * F16_STAGE;                               \
            uint32_t doff_ = (uint32_t)(lrow * 80 + lc * 16);                     \
            cp16(st_ + doff_,          A + (size_t)(cx.bm + lrow) * 1024 + (k0) + lc * 8); \
            cp16(st_ + TILE_B + doff_, B + (size_t)(cx.bn + lrow) * 1024 + (k0) + lc * 8); \
        } while (0)

    const uint32_t a_roff = (uint32_t)((cx.wm * 32 + (lane & 15)) * 80 + (lane >> 4) * 16);
    const uint32_t b_row  = (uint32_t)((lane & 7) | ((lane & 16) >> 1));
    const uint32_t b_roff = (uint32_t)((cx.wn * 32 + b_row) * 80 + ((lane >> 3) & 1) * 16);

    F16_LOAD(0, 0);
    CP_COMMIT();
    F16_LOAD(1, 32);
    CP_COMMIT();

    const int NIT = 1024 / 32;
    int stg = 0;
    for (int it = 0; it < NIT; it++) {
        CP_WAIT1();
        __syncthreads();
        if (it + 2 < NIT) F16_LOAD((stg + 2) % 3, (it + 2) * 32);
        CP_COMMIT();

        const uint32_t sA = smb + stg * F16_STAGE;
        const uint32_t sB = sA + TILE_B;

        #pragma unroll
        for (int ks = 0; ks < 2; ks++) {
            uint32_t af[2][4], bf_[2][4];
            uint32_t ao = a_roff + ks * 32;
            ldsm4(af[0], sA + ao);
            ldsm4(af[1], sA + ao + 16 * 80);
            uint32_t bo = b_roff + ks * 32;
            ldsm4(bf_[0], sB + bo);
            ldsm4(bf_[1], sB + bo + 16 * 80);
            #pragma unroll
            for (int mf = 0; mf < 2; mf++)
                #pragma unroll
                for (int nf = 0; nf < 4; nf++) {
                    int g = nf >> 1, o = (nf & 1) * 2;
                    mma16816h(acc[mf][nf], af[mf], bf_[g][o], bf_[g][o + 1]);
                }
        }
        stg = (stg + 1) % 3;
    }
    #undef F16_LOAD
}

// ---------------------------------------------------------------------------
// QKV GEMM with fused repack epilogue: writes q (fp16 head-major, x0.125),
// k (fp16 head-major), v^T (fp16 [bh][d][n]) directly.
// ---------------------------------------------------------------------------
__global__ __launch_bounds__(512, 2) void tc_gemm_qkv(
    const __half* __restrict__ A, const __half* __restrict__ B,
    const float* __restrict__ bias,
    __half* __restrict__ qf, __half* __restrict__ kf, __half* __restrict__ vtf)
{
    extern __shared__ char sm[];
    GemmCtx cx;
    float acc[2][4][4];
    gemm_mainloop_f16(sm, A, B, cx, acc);

    const int region = cx.bn >> 10;          // 0=q, 1=k, 2=v
    const int rbase = cx.bm + cx.wm * 32 + (cx.lane >> 2);
    #pragma unroll
    for (int nf = 0; nf < 4; nf++) {
        int col = cx.bn + cx.wn * 32 + nf * 8 + (cx.lane & 3) * 2;
        float b0 = __ldg(&bias[col]);
        float b1 = __ldg(&bias[col + 1]);
        int c = col & 1023;
        int h = c >> 6, d = c & 63;
        #pragma unroll
        for (int mf = 0; mf < 2; mf++) {
            #pragma unroll
            for (int rr = 0; rr < 2; rr++) {
                int row = rbase + mf * 16 + rr * 8;
                float x0 = acc[mf][nf][rr * 2 + 0] + b0;
                float x1 = acc[mf][nf][rr * 2 + 1] + b1;
                int b = row >> 11, n = row & 2047;
                if (region == 0) {
                    size_t oi = ((size_t)(b * HH + h) * NN + n) * HD + d;
                    *(__half2*)(qf + oi) = __floats2half2_rn(x0 * 0.125f, x1 * 0.125f);
                } else if (region == 1) {
                    size_t oi = ((size_t)(b * HH + h) * NN + n) * HD + d;
                    *(__half2*)(kf + oi) = __floats2half2_rn(x0, x1);
                } else {
                    size_t oi = ((size_t)(b * HH + h) * HD + d) * NN + n;
                    vtf[oi]      = __float2half_rn(x0);
                    vtf[oi + NN] = __float2half_rn(x1);
                }
            }
        }
    }
}

// ---------------------------------------------------------------------------
// Output projection GEMM (standard fp32 epilogue to d_out)
// ---------------------------------------------------------------------------
__global__ __launch_bounds__(512, 2) void tc_gemm_proj(
    const __half* __restrict__ A, const __half* __restrict__ B,
    const float* __restrict__ bias, float* __restrict__ C)
{
    extern __shared__ char sm[];
    GemmCtx cx;
    float acc[2][4][4];
    gemm_mainloop_f16(sm, A, B, cx, acc);

    #pragma unroll
    for (int nf = 0; nf < 4; nf++) {
        int col = cx.bn + cx.wn * 32 + nf * 8 + (cx.lane & 3) * 2;
        float b0 = __ldg(&bias[col]);
        float b1 = __ldg(&bias[col + 1]);
        #pragma unroll
        for (int mf = 0; mf < 2; mf++) {
            int row0 = cx.bm + cx.wm * 32 + mf * 16 + (cx.lane >> 2);
            float2 v0 = make_float2(acc[mf][nf][0] + b0, acc[mf][nf][1] + b1);
            float2 v1 = make_float2(acc[mf][nf][2] + b0, acc[mf][nf][3] + b1);
            *(float2*)&C[(size_t)row0 * DDIM + col]       = v0;
            *(float2*)&C[(size_t)(row0 + 8) * DDIM + col] = v1;
        }
    }
}

// ---------------------------------------------------------------------------
// Flash attention via fp16 mma.sync (S single, P single x V single).
// __launch_bounds__(256, 1): register-resident (2 CTA/SM capped regs and
// spilled the hot loop — measured regression in round 15).
// Epilogue writes fp16 directly into g_ah.
// ---------------------------------------------------------------------------
#define AT_KSTR 72
#define AT_VSTR 136
#define AT_K_B  (128 * AT_KSTR * 2)
#define AT_V_B  (64 * AT_VSTR * 2)
#define AT_STAGE_B (AT_K_B + AT_V_B)                // 35840 bytes
#define ATT_SMEM (2 * AT_STAGE_B)                   // 71680 bytes

__global__ __launch_bounds__(256, 1) void attn_mma(
    const __half* __restrict__ qf, const __half* __restrict__ kf,
    const __half* __restrict__ vtf, __half* __restrict__ outh)
{
    extern __shared__ __half sbh[];
    __half* sK0 = sbh;
    const uint32_t aK = smem_u32(sK0);
    const uint32_t aV = aK + AT_K_B;

    const int tid = threadIdx.x, lane = tid & 31, w = tid >> 5;
    const int qt = 15 - (int)blockIdx.x;
    const int bh = blockIdx.y;
    const int b = bh >> 4, h = bh & 15;
    const size_t hb = (size_t)bh * (NN * HD);
    const size_t vb = (size_t)bh * (HD * NN);

    const int r8  = tid >> 3, c8 = tid & 7;
    const int r16v = tid >> 4, c16v = tid & 15;
    const uint32_t brow = (uint32_t)((lane & 7) | ((lane & 16) >> 1));
    const uint32_t bcol8 = (uint32_t)(((lane >> 3) & 1) * 8);

    #define AT_LOAD(stg_, kt_)                                                    \
        do {                                                                      \
            uint32_t kb_ = (uint32_t)(stg_) * AT_STAGE_B;                         \
            int kv0_ = (kt_) * 128;                                               \
            _Pragma("unroll")                                                     \
            for (int i_ = 0; i_ < 4; i_++) {                                      \
                int r_ = i_ * 32 + r8;                                            \
                cp16(aK + kb_ + (uint32_t)(r_ * AT_KSTR + c8 * 8) * 2,            \
                     kf + hb + (size_t)(kv0_ + r_) * HD + c8 * 8);                \
            }                                                                     \
            _Pragma("unroll")                                                     \
            for (int i_ = 0; i_ < 4; i_++) {                                      \
                int d_ = i_ * 16 + r16v;                                          \
                cp16(aV + kb_ + (uint32_t)(d_ * AT_VSTR + c16v * 8) * 2,          \
                     vtf + vb + (size_t)d_ * NN + kv0_ + c16v * 8);               \
            }                                                                     \
        } while (0)

    // ---- stage Q into stage-0 K buffer, extract A-frags ----
    #pragma unroll
    for (int i = 0; i < 4; i++) {
        int r = i * 32 + r8;
        size_t g = hb + (size_t)(qt * 128 + r) * HD + c8 * 8;
        *(uint4*)(sK0 + r * AT_KSTR + c8 * 8) = *(const uint4*)(qf + g);
    }
    __syncthreads();
    uint32_t qfr[4][4];
    #pragma unroll
    for (int ks = 0; ks < 4; ks++) {
        uint32_t off = (uint32_t)(((w * 16 + (lane & 15)) * AT_KSTR
                                   + (lane >> 4) * 8 + ks * 16) * 2);
        ldsm4(qfr[ks], aK + off);
    }
    __syncthreads();

    float m0 = -1e30f, m1 = -1e30f, l0 = 0.f, l1 = 0.f;
    float o[8][4];
    #pragma unroll
    for (int i = 0; i < 8; i++)
        #pragma unroll
        for (int j = 0; j < 4; j++) o[i][j] = 0.f;

    const int nkv = qt + 1;
    AT_LOAD(0, 0);
    CP_COMMIT();

    for (int kt = 0; kt < nkv; kt++) {
        const int stg = kt & 1;
        if (kt + 1 < nkv) AT_LOAD(stg ^ 1, kt + 1);
        CP_COMMIT();
        CP_WAIT1();
        __syncthreads();

        const uint32_t kb = (uint32_t)stg * AT_STAGE_B;
        const uint32_t bK = aK + kb, bV = aV + kb;

        float s[16][4];
        #pragma unroll
        for (int i = 0; i < 16; i++)
            #pragma unroll
            for (int j = 0; j < 4; j++) s[i][j] = 0.f;

        #pragma unroll
        for (int g = 0; g < 8; g++) {
            #pragma unroll
            for (int ks = 0; ks < 4; ks++) {
                uint32_t kfr[4];
                uint32_t off = (uint32_t)((((g * 16) + brow) * AT_KSTR
                                           + bcol8 + ks * 16) * 2);
                ldsm4(kfr, bK + off);
                #pragma unroll
                for (int nf2 = 0; nf2 < 2; nf2++)
                    mma16816h(s[g * 2 + nf2], qfr[ks], kfr[nf2 * 2], kfr[nf2 * 2 + 1]);
            }
        }

        if (kt == qt) {
            int row0 = w * 16 + (lane >> 2);
            #pragma unroll
            for (int nf = 0; nf < 16; nf++) {
                int col = nf * 8 + (lane & 3) * 2;
                if (col > row0)     s[nf][0] = -1e30f;
                if (col + 1 > row0) s[nf][1] = -1e30f;
                if (col > row0 + 8)     s[nf][2] = -1e30f;
                if (col + 1 > row0 + 8) s[nf][3] = -1e30f;
            }
        }

        float mt0 = -1e30f, mt1 = -1e30f;
        #pragma unroll
        for (int nf = 0; nf < 16; nf++) {
            mt0 = fmaxf(mt0, fmaxf(s[nf][0], s[nf][1]));
            mt1 = fmaxf(mt1, fmaxf(s[nf][2], s[nf][3]));
        }
        mt0 = fmaxf(mt0, __shfl_xor_sync(0xffffffffu, mt0, 1));
        mt0 = fmaxf(mt0, __shfl_xor_sync(0xffffffffu, mt0, 2));
        mt1 = fmaxf(mt1, __shfl_xor_sync(0xffffffffu, mt1, 1));
        mt1 = fmaxf(mt1, __shfl_xor_sync(0xffffffffu, mt1, 2));
        float mn0 = fmaxf(m0, mt0), mn1 = fmaxf(m1, mt1);
        float cr0 = __expf(m0 - mn0), cr1 = __expf(m1 - mn1);
        float rs0 = 0.f, rs1 = 0.f;
        #pragma unroll
        for (int nf = 0; nf < 16; nf++) {
            s[nf][0] = __expf(s[nf][0] - mn0);
            s[nf][1] = __expf(s[nf][1] - mn0);
            s[nf][2] = __expf(s[nf][2] - mn1);
            s[nf][3] = __expf(s[nf][3] - mn1);
            rs0 += s[nf][0] + s[nf][1];
            rs1 += s[nf][2] + s[nf][3];
        }
        rs0 += __shfl_xor_sync(0xffffffffu, rs0, 1);
        rs0 += __shfl_xor_sync(0xffffffffu, rs0, 2);
        rs1 += __shfl_xor_sync(0xffffffffu, rs1, 1);
        rs1 += __shfl_xor_sync(0xffffffffu, rs1, 2);
        l0 = l0 * cr0 + rs0;
        l1 = l1 * cr1 + rs1;
        m0 = mn0; m1 = mn1;
        #pragma unroll
        for (int nf = 0; nf < 8; nf++) {
            o[nf][0] *= cr0; o[nf][1] *= cr0;
            o[nf][2] *= cr1; o[nf][3] *= cr1;
        }

        // ---- O += P V : P fp16 single, V fp16 single ----
        #pragma unroll
        for (int ks2 = 0; ks2 < 8; ks2++) {
            uint32_t pa[4];
            {
                const float* s0 = s[2 * ks2];
                const float* s1 = s[2 * ks2 + 1];
                pa[0] = packhf(s0[0], s0[1]);
                pa[1] = packhf(s0[2], s0[3]);
                pa[2] = packhf(s1[0], s1[1]);
                pa[3] = packhf(s1[2], s1[3]);
            }
            #pragma unroll
            for (int g = 0; g < 4; g++) {
                uint32_t vfr[4];
                uint32_t off = (uint32_t)((((g * 16) + brow) * AT_VSTR
                                           + bcol8 + ks2 * 16) * 2);
                ldsm4(vfr, bV + off);
                #pragma unroll
                for (int nf2 = 0; nf2 < 2; nf2++) {
                    int nf = g * 2 + nf2, oo = nf2 * 2;
                    mma16816h(o[nf], pa, vfr[oo], vfr[oo + 1]);
                }
            }
        }
        __syncthreads();
    }

    // finalize: write fp16 directly into proj input buffer
    float inv0 = 1.f / l0, inv1 = 1.f / l1;
    const int row0 = b * NN + qt * 128 + w * 16 + (lane >> 2);
    #pragma unroll
    for (int nf = 0; nf < 8; nf++) {
        int col = h * HD + nf * 8 + (lane & 3) * 2;
        *(__half2*)&outh[(size_t)row0 * DDIM + col] =
            __floats2half2_rn(o[nf][0] * inv0, o[nf][1] * inv0);
        *(__half2*)&outh[(size_t)(row0 + 8) * DDIM + col] =
            __floats2half2_rn(o[nf][2] * inv1, o[nf][3] * inv1);
    }
}

// ---------------------------------------------------------------------------
// Launch
// ---------------------------------------------------------------------------
extern "C" void kernel_launch(void* const* d_in, const int* in_sizes, int n_in,
                              void* d_out, int out_size) {
    const float* hs     = (const float*)d_in[0];
    const float* W_attn = (const float*)d_in[1];
    const float* b_attn = (const float*)d_in[2];
    const float* W_proj = (const float*)d_in[3];
    const float* b_proj = (const float*)d_in[4];
    float* out = (float*)d_out;

    cudaFuncSetAttribute(attn_mma,
                         cudaFuncAttributeMaxDynamicSharedMemorySize, ATT_SMEM);
    cudaFuncSetAttribute(tc_gemm_qkv,
                         cudaFuncAttributeMaxDynamicSharedMemorySize, F16_SMEM);
    cudaFuncSetAttribute(tc_gemm_proj,
                         cudaFuncAttributeMaxDynamicSharedMemorySize, F16_SMEM);

    __half *ah, *wqt, *wpt, *qf, *kf, *vtf;
    cudaGetSymbolAddress((void**)&ah,   g_ah);
    cudaGetSymbolAddress((void**)&wqt,  g_wqt);
    cudaGetSymbolAddress((void**)&wpt,  g_wpt);
    cudaGetSymbolAddress((void**)&qf,   g_qf);
    cudaGetSymbolAddress((void**)&kf,   g_kf);
    cudaGetSymbolAddress((void**)&vtf,  g_vtf);

    // 1) fused prep: hs->fp16 + both weight transposes
    prep_all<<<PREP_BLKS, 256>>>(hs, W_attn, W_proj, ah, wqt, wpt);
    // 2) QKV projection + fused q/k/v repack
    tc_gemm_qkv<<<dim3(N3D / 128, MROWS / 128), 512, F16_SMEM>>>(
        ah, wqt, b_attn, qf, kf, vtf);
    // 3) causal flash attention (fp16 tensor cores), writes fp16 into g_ah
    attn_mma<<<dim3(NN / 128, BB * HH), 256, ATT_SMEM>>>(qf, kf, vtf, ah);
    // 4) output projection
    tc_gemm_proj<<<dim3(DDIM / 128, MROWS / 128), 512, F16_SMEM>>>(
        ah, wpt, b_proj, out);
}